// round 16
// baseline (speedup 1.0000x reference)
#include <cuda_runtime.h>
#include <cuda_fp16.h>
#include <cstdint>

// Problem constants
#define BB 4
#define LL 1024
#define CC 1280
#define HH 20
#define DH 64
#define BHH (BB*HH)        // 80
#define BANK 40
#define LPOOL 256          // (32/2)*(32/2)
#define LKV (LL + LPOOL)   // 1280
#define ALPHA_C 0.48f      // 0.8 * 0.6
#define QSCALE 0.125f      // 1/sqrt(64)
#define LOG2E 1.4426950408889634f

#define MROWS (BB*LL)      // 4096

// Scratch (device globals are allowed; cudaMalloc is not)
__device__ __half g_qh[MROWS*CC];             // Q fp16, pre-scaled by QSCALE*log2e
__device__ __half g_hsh[MROWS*CC];            // hs in fp16
__device__ __half g_wh[4][CC*CC];             // Wq,Wk,Wv,Wo in fp16
__device__ __half g_ctxh[MROWS*CC];           // attention output in fp16
__device__ __half g_kh[(size_t)BHH*LKV*DH];   // fused main+bank K, fp16 head-major
__device__ __half g_vh[(size_t)BHH*LKV*DH];

__device__ __forceinline__ float fp16_round(float x) {
    return __half2float(__float2half_rn(x));
}
__device__ __forceinline__ float ex2f(float x) {
    float y;
    asm("ex2.approx.ftz.f32 %0, %1;" : "=f"(y) : "f"(x));
    return y;
}
__device__ __forceinline__ void mma_f16(float* d, const unsigned* a, unsigned b0, unsigned b1) {
    asm volatile(
        "mma.sync.aligned.m16n8k16.row.col.f32.f16.f16.f32 "
        "{%0,%1,%2,%3}, {%4,%5,%6,%7}, {%8,%9}, {%0,%1,%2,%3};\n"
        : "+f"(d[0]), "+f"(d[1]), "+f"(d[2]), "+f"(d[3])
        : "r"(a[0]), "r"(a[1]), "r"(a[2]), "r"(a[3]),
          "r"(b0), "r"(b1));
}
__device__ __forceinline__ void cp16(uint32_t saddr, const void* gptr) {
    asm volatile("cp.async.cg.shared.global [%0], [%1], 16;\n"
                 :: "r"(saddr), "l"(gptr));
}
__device__ __forceinline__ void ldsm_x4(unsigned& r0, unsigned& r1, unsigned& r2,
                                        unsigned& r3, uint32_t a) {
    asm volatile("ldmatrix.sync.aligned.m8n8.x4.shared.b16 {%0,%1,%2,%3}, [%4];\n"
                 : "=r"(r0), "=r"(r1), "=r"(r2), "=r"(r3) : "r"(a));
}
__device__ __forceinline__ void ldsm_x4_t(unsigned& r0, unsigned& r1, unsigned& r2,
                                          unsigned& r3, uint32_t a) {
    asm volatile("ldmatrix.sync.aligned.m8n8.x4.trans.shared.b16 {%0,%1,%2,%3}, [%4];\n"
                 : "=r"(r0), "=r"(r1), "=r"(r2), "=r"(r3) : "r"(a));
}

// ---------------------------------------------------------------------------
// fp32 -> fp16 conversion: hs + 4 weight matrices, 8 elems/thread
// ---------------------------------------------------------------------------
#define HS_N8 (MROWS*CC/8)    // 655360
#define W_N8  (CC*CC/8)       // 204800

__global__ void cvt_kernel(const float* __restrict__ hs,
                           const float* __restrict__ Wq, const float* __restrict__ Wk,
                           const float* __restrict__ Wv, const float* __restrict__ Wo) {
    int idx = blockIdx.x * blockDim.x + threadIdx.x;
    const float* src;
    __half* dst;
    long off;
    if (idx < HS_N8) {
        src = hs; dst = g_hsh; off = (long)idx * 8;
    } else {
        int i2 = idx - HS_N8;
        int w = i2 / W_N8;
        if (w >= 4) return;
        off = (long)(i2 % W_N8) * 8;
        src = (w == 0) ? Wq : (w == 1) ? Wk : (w == 2) ? Wv : Wo;
        dst = g_wh[w];
    }
    float4 a = *(const float4*)(src + off);
    float4 b = *(const float4*)(src + off + 4);
    __half2 h0 = __floats2half2_rn(a.x, a.y);
    __half2 h1 = __floats2half2_rn(a.z, a.w);
    __half2 h2 = __floats2half2_rn(b.x, b.y);
    __half2 h3 = __floats2half2_rn(b.z, b.w);
    uint4 pack;
    pack.x = *(unsigned*)&h0; pack.y = *(unsigned*)&h1;
    pack.z = *(unsigned*)&h2; pack.w = *(unsigned*)&h3;
    *(uint4*)(dst + off) = pack;
}

// ---------------------------------------------------------------------------
// Bank KV: fp16 round -> 2x2 avg pool -> *ALPHA, write fp16 rows [1024..1279]
// of g_kh/g_vh for BOTH bh and bh+40 (bank repeats across batch).
// ---------------------------------------------------------------------------
__global__ void pool_kernel(const float* __restrict__ Kg,
                            const float* __restrict__ Vg) {
    int idx = blockIdx.x * blockDim.x + threadIdx.x;
    const int total = BANK * LPOOL * DH;
    if (idx >= total) return;
    int d  = idx % DH;
    int p  = (idx / DH) % LPOOL;
    int bh = idx / (DH * LPOOL);
    int ph = p >> 4;
    int pw = p & 15;
    int t0 = (2 * ph) * 32 + 2 * pw;
    long base = ((long)bh * LL + t0) * DH + d;

    float ks = fp16_round(Kg[base])         + fp16_round(Kg[base + DH])
             + fp16_round(Kg[base + 32*DH]) + fp16_round(Kg[base + 33*DH]);
    float vs = fp16_round(Vg[base])         + fp16_round(Vg[base + DH])
             + fp16_round(Vg[base + 32*DH]) + fp16_round(Vg[base + 33*DH]);
    __half kq = __float2half(ALPHA_C * (ks * 0.25f));
    __half vq = __float2half(ALPHA_C * (vs * 0.25f));
#pragma unroll
    for (int rep = 0; rep < 2; rep++) {
        long dst = ((long)(bh + rep * BANK) * LKV + LL + p) * DH + d;
        g_kh[dst] = kq;
        g_vh[dst] = vq;
    }
}

// ---------------------------------------------------------------------------
// fp16 tensor-core GEMM, 3-stage cp.async pipeline, ONE barrier per k-tile.
// MT=4 -> 128-row tile, fused QKV: mat0 -> Q fp16 prescaled, mat1/2 -> K/V
// head-major fp16. MT=2 -> 64-row tile, Wo: fp32 out + bias (grid 640).
// ---------------------------------------------------------------------------
#define BKH 32
#define APADH 40
#define BPADH 136
#define NTN (CC/128)   // 10 n-tiles per matrix

template<int MT>
__global__ __launch_bounds__(256)
void hgemm_kernel(const __half* __restrict__ A,
                  const __half* __restrict__ W0, const __half* __restrict__ W1,
                  const __half* __restrict__ W2, const float* __restrict__ bias,
                  float* __restrict__ C0, __half* __restrict__ HQ,
                  __half* __restrict__ HK, __half* __restrict__ HV,
                  int M, int N, int K) {
    extern __shared__ __half sm[];
    constexpr int AROWS = MT * 32;
    constexpr uint32_t ASZB = AROWS * APADH * 2u;   // bytes per A stage
    constexpr uint32_t BSZB = BKH * BPADH * 2u;     // bytes per B stage

    int tid  = threadIdx.x;
    int lane = tid & 31;
    int wid  = tid >> 5;
    int wm   = wid >> 2;          // 0..1
    int wn   = wid & 3;           // 0..3
    int g    = lane >> 2;
    int tg   = lane & 3;
    int mm   = lane >> 3;         // 0..3 (ldmatrix sub-matrix)
    int r5   = lane & 7;

    int mat = blockIdx.x / NTN;
    int ntile = blockIdx.x % NTN;
    const __half* W = (mat == 0) ? W0 : (mat == 1) ? W1 : W2;

    int m0 = blockIdx.y * AROWS;
    int n0 = ntile * 128;

    // cp.async mappings (halves)
    int arow = (MT == 4) ? (tid >> 1) : (tid >> 2);
    int acol = (MT == 4) ? ((tid & 1) * 16) : ((tid & 3) * 8);
    int brow = tid >> 3;
    int bcol = (tid & 7) * 16;

    uint32_t smem_u = (uint32_t)__cvta_generic_to_shared(sm);
    uint32_t aswb = smem_u + (uint32_t)(arow * APADH + acol) * 2u;
    uint32_t bswb = smem_u + 3u * ASZB + (uint32_t)(brow * BPADH + bcol) * 2u;

    const __half* agp = A + (long)(m0 + arow) * K + acol;
    const __half* bgp = W + (long)brow * N + n0 + bcol;

    auto issue = [&](int tile, int s) {
        const __half* ag = agp + tile * BKH;
        const __half* bg = bgp + (long)tile * BKH * N;
        uint32_t ad = aswb + (uint32_t)s * ASZB;
        uint32_t bd = bswb + (uint32_t)s * BSZB;
        cp16(ad, ag);
        if (MT == 4) cp16(ad + 16, ag + 8);
        cp16(bd, bg);
        cp16(bd + 16, bg + 8);
        asm volatile("cp.async.commit_group;\n");
    };

    float acc[MT][4][4];
#pragma unroll
    for (int i = 0; i < MT; i++)
#pragma unroll
        for (int j = 0; j < 4; j++)
#pragma unroll
            for (int r = 0; r < 4; r++) acc[i][j][r] = 0.f;

    const int NT = K / BKH;   // 40

    issue(0, 0);
    issue(1, 1);

    for (int t = 0; t < NT; t++) {
        int s = t % 3;
        if (t < NT - 1) asm volatile("cp.async.wait_group 1;\n");
        else            asm volatile("cp.async.wait_group 0;\n");
        __syncthreads();
        if (t + 2 < NT) issue(t + 2, (t + 2) % 3);

        uint32_t aS = smem_u + (uint32_t)s * ASZB;
        uint32_t bS = smem_u + 3u * ASZB + (uint32_t)s * BSZB;

#pragma unroll
        for (int tt = 0; tt < 2; tt++) {
            unsigned af[MT][4];
#pragma unroll
            for (int mf = 0; mf < MT; mf++) {
                int row = wm * (MT * 16) + mf * 16 + (mm & 1) * 8 + r5;
                uint32_t a = aS + (uint32_t)((row * APADH + tt * 16 + (mm >> 1) * 8) * 2);
                ldsm_x4(af[mf][0], af[mf][1], af[mf][2], af[mf][3], a);
            }
#pragma unroll
            for (int j2 = 0; j2 < 2; j2++) {
                unsigned b0, b1, b2, b3;
                int krow = tt * 16 + (mm & 1) * 8 + r5;
                int col  = wn * 32 + j2 * 16 + (mm >> 1) * 8;
                uint32_t a = bS + (uint32_t)((krow * BPADH + col) * 2);
                ldsm_x4_t(b0, b1, b2, b3, a);
#pragma unroll
                for (int mf = 0; mf < MT; mf++) {
                    mma_f16(acc[mf][2 * j2],     af[mf], b0, b1);
                    mma_f16(acc[mf][2 * j2 + 1], af[mf], b2, b3);
                }
            }
        }
    }

    // Epilogue
    if (MT == 2) {
        // Wo: fp32 out + bias
#pragma unroll
        for (int mf = 0; mf < MT; mf++) {
            long r0 = m0 + wm * (MT * 16) + mf * 16 + g;
#pragma unroll
            for (int nf = 0; nf < 4; nf++) {
                int c = n0 + wn * 32 + nf * 8 + tg * 2;
                float b0 = bias ? bias[c] : 0.f;
                float b1 = bias ? bias[c + 1] : 0.f;
                float2 v0 = {acc[mf][nf][0] + b0, acc[mf][nf][1] + b1};
                float2 v1 = {acc[mf][nf][2] + b0, acc[mf][nf][3] + b1};
                *(float2*)(C0 + r0 * N + c)       = v0;
                *(float2*)(C0 + (r0 + 8) * N + c) = v1;
            }
        }
    } else if (mat == 0) {
        // Q: fp16, pre-scaled by QSCALE*log2e, [M, C] row-major
        const float sca = QSCALE * LOG2E;
#pragma unroll
        for (int mf = 0; mf < MT; mf++) {
            long r0 = m0 + wm * (MT * 16) + mf * 16 + g;
#pragma unroll
            for (int nf = 0; nf < 4; nf++) {
                int c = n0 + wn * 32 + nf * 8 + tg * 2;
#pragma unroll
                for (int rr = 0; rr < 2; rr++) {
                    long row = r0 + rr * 8;
                    __half2 hv = __floats2half2_rn(acc[mf][nf][rr * 2] * sca,
                                                   acc[mf][nf][rr * 2 + 1] * sca);
                    *(__half2*)(HQ + row * N + c) = hv;
                }
            }
        }
    } else {
        __half* H = (mat == 1) ? HK : HV;
#pragma unroll
        for (int mf = 0; mf < MT; mf++) {
            int r0 = m0 + wm * (MT * 16) + mf * 16 + g;
#pragma unroll
            for (int nf = 0; nf < 4; nf++) {
                int c = n0 + wn * 32 + nf * 8 + tg * 2;
                int h = c >> 6, d = c & 63;
#pragma unroll
                for (int rr = 0; rr < 2; rr++) {
                    int row = r0 + rr * 8;
                    int b = row >> 10, l = row & 1023;
                    long dst = ((long)(b * HH + h) * LKV + l) * DH + d;
                    __half2 hv = __floats2half2_rn(acc[mf][nf][rr * 2],
                                                   acc[mf][nf][rr * 2 + 1]);
                    *(__half2*)(&H[dst]) = hv;
                }
            }
        }
    }
}

// ---------------------------------------------------------------------------
// Flash attention, fp16 HMMA. Block = (head, 128 q rows), 8 warps, 3-stage KV
// pipeline, one barrier per KV tile. Q read as pre-scaled fp16 fragments.
// ---------------------------------------------------------------------------
#define KPAD 72
#define KVSTG (2 * 64 * KPAD * 2)   // bytes per stage (K+V) = 18432

__global__ __launch_bounds__(256)
void flash_tc_kernel(const __half* __restrict__ qh, const __half* __restrict__ kh,
                     const __half* __restrict__ vh, __half* __restrict__ ctxh) {
    extern __shared__ __half skv[];

    int tid  = threadIdx.x;
    int lane = tid & 31;
    int w    = tid >> 5;
    int g    = lane >> 2;
    int tg   = lane & 3;
    int mm   = lane >> 3;
    int r5   = lane & 7;
    int bh = blockIdx.y;
    int bb = bh / HH;
    int hh = bh % HH;
    int q0 = blockIdx.x * 128;
    int qrow = q0 + w * 16 + g;

    // Q fragments: direct fp16 loads (pre-scaled in GEMM epilogue)
    unsigned qa[4][4];
    {
        const __half* qp = qh + ((long)bb * LL + qrow) * CC + hh * DH;
#pragma unroll
        for (int t = 0; t < 4; t++) {
            qa[t][0] = *(const unsigned*)(qp + 16 * t + 2 * tg);
            qa[t][1] = *(const unsigned*)(qp + 8 * CC + 16 * t + 2 * tg);
            qa[t][2] = *(const unsigned*)(qp + 16 * t + 8 + 2 * tg);
            qa[t][3] = *(const unsigned*)(qp + 8 * CC + 16 * t + 8 + 2 * tg);
        }
    }

    int tsel = tid >> 7;
    int idxl = tid & 127;
    int lrow = idxl >> 1;
    int lhf  = idxl & 1;
    const __half* gsrc0 = (tsel ? vh : kh) + ((long)bh * LKV + lrow) * DH + lhf * 32;
    uint32_t sbase = (uint32_t)__cvta_generic_to_shared(skv);
    uint32_t sdst0 = sbase + (uint32_t)(tsel * (64 * KPAD) + lrow * KPAD + lhf * 32) * 2u;

    auto issue = [&](int tile, int s) {
        const __half* src = gsrc0 + (long)tile * 64 * DH;
        uint32_t dd = sdst0 + (uint32_t)s * KVSTG;
#pragma unroll
        for (int i = 0; i < 4; i++) cp16(dd + i * 16, src + i * 8);
        asm volatile("cp.async.commit_group;\n");
    };

    float m0v = -1e30f, m1v = -1e30f, l0 = 0.f, l1 = 0.f;
    float O[8][4];
#pragma unroll
    for (int j = 0; j < 8; j++)
#pragma unroll
        for (int r = 0; r < 4; r++) O[j][r] = 0.f;

    const int NT = LKV / 64;   // 20

    issue(0, 0);
    issue(1, 1);

    for (int t = 0; t < NT; t++) {
        int s = t % 3;
        if (t < NT - 1) asm volatile("cp.async.wait_group 1;\n");
        else            asm volatile("cp.async.wait_group 0;\n");
        __syncthreads();
        if (t + 2 < NT) issue(t + 2, (t + 2) % 3);

        uint32_t kbase = sbase + (uint32_t)s * KVSTG;
        uint32_t vbase = kbase + (uint32_t)(64 * KPAD) * 2u;

        // S = Q K^T (log2 domain)
        float sacc[8][4];
#pragma unroll
        for (int j = 0; j < 8; j++)
#pragma unroll
            for (int r = 0; r < 4; r++) sacc[j][r] = 0.f;

#pragma unroll
        for (int tt = 0; tt < 4; tt++) {
#pragma unroll
            for (int j2 = 0; j2 < 4; j2++) {
                unsigned b0, b1, b2, b3;
                uint32_t a = kbase +
                    (uint32_t)(((j2 * 16 + (mm >> 1) * 8 + r5) * KPAD
                                + tt * 16 + (mm & 1) * 8) * 2);
                ldsm_x4(b0, b1, b2, b3, a);
                mma_f16(sacc[2 * j2],     qa[tt], b0, b1);
                mma_f16(sacc[2 * j2 + 1], qa[tt], b2, b3);
            }
        }

        // Online softmax
        float mx0 = -1e30f, mx1 = -1e30f;
#pragma unroll
        for (int j = 0; j < 8; j++) {
            mx0 = fmaxf(mx0, fmaxf(sacc[j][0], sacc[j][1]));
            mx1 = fmaxf(mx1, fmaxf(sacc[j][2], sacc[j][3]));
        }
        mx0 = fmaxf(mx0, __shfl_xor_sync(0xffffffffu, mx0, 1));
        mx0 = fmaxf(mx0, __shfl_xor_sync(0xffffffffu, mx0, 2));
        mx1 = fmaxf(mx1, __shfl_xor_sync(0xffffffffu, mx1, 1));
        mx1 = fmaxf(mx1, __shfl_xor_sync(0xffffffffu, mx1, 2));

        float mn0 = fmaxf(m0v, mx0);
        float mn1 = fmaxf(m1v, mx1);
        float sc0 = ex2f(m0v - mn0);
        float sc1 = ex2f(m1v - mn1);
        m0v = mn0; m1v = mn1;

        // exp in place
        float su0 = 0.f, su1 = 0.f;
#pragma unroll
        for (int j = 0; j < 8; j++) {
            sacc[j][0] = ex2f(sacc[j][0] - mn0);
            sacc[j][1] = ex2f(sacc[j][1] - mn0);
            sacc[j][2] = ex2f(sacc[j][2] - mn1);
            sacc[j][3] = ex2f(sacc[j][3] - mn1);
            su0 += sacc[j][0] + sacc[j][1];
            su1 += sacc[j][2] + sacc[j][3];
        }
        su0 += __shfl_xor_sync(0xffffffffu, su0, 1);
        su0 += __shfl_xor_sync(0xffffffffu, su0, 2);
        su1 += __shfl_xor_sync(0xffffffffu, su1, 1);
        su1 += __shfl_xor_sync(0xffffffffu, su1, 2);
        l0 = l0 * sc0 + su0;
        l1 = l1 * sc1 + su1;

#pragma unroll
        for (int j = 0; j < 8; j++) {
            O[j][0] *= sc0; O[j][1] *= sc0;
            O[j][2] *= sc1; O[j][3] *= sc1;
        }

        // Pack P fragments directly from accumulators (C layout == A layout)
        unsigned paf[4][4];
#pragma unroll
        for (int tt = 0; tt < 4; tt++) {
            __half2 a0 = __floats2half2_rn(sacc[2*tt][0],   sacc[2*tt][1]);
            __half2 a1 = __floats2half2_rn(sacc[2*tt][2],   sacc[2*tt][3]);
            __half2 a2 = __floats2half2_rn(sacc[2*tt+1][0], sacc[2*tt+1][1]);
            __half2 a3 = __floats2half2_rn(sacc[2*tt+1][2], sacc[2*tt+1][3]);
            paf[tt][0] = *(unsigned*)&a0;
            paf[tt][1] = *(unsigned*)&a1;
            paf[tt][2] = *(unsigned*)&a2;
            paf[tt][3] = *(unsigned*)&a3;
        }

        // O += P V  (V^T fragments via ldmatrix.trans)
#pragma unroll
        for (int tt = 0; tt < 4; tt++) {
#pragma unroll
            for (int j2 = 0; j2 < 4; j2++) {
                unsigned b0, b1, b2, b3;
                uint32_t a = vbase +
                    (uint32_t)(((tt * 16 + (mm & 1) * 8 + r5) * KPAD
                                + j2 * 16 + (mm >> 1) * 8) * 2);
                ldsm_x4_t(b0, b1, b2, b3, a);
                mma_f16(O[2 * j2],     paf[tt], b0, b1);
                mma_f16(O[2 * j2 + 1], paf[tt], b2, b3);
            }
        }
    }

    // Normalize + write ctx (fp16) in [B, L, H*Dh]
    float inv0 = 1.f / l0;
    float inv1 = 1.f / l1;
    __half* cp0 = ctxh + ((long)bb * LL + qrow) * CC + hh * DH;
#pragma unroll
    for (int j = 0; j < 8; j++) {
        __half2 v0 = __floats2half2_rn(O[j][0] * inv0, O[j][1] * inv0);
        __half2 v1 = __floats2half2_rn(O[j][2] * inv1, O[j][3] * inv1);
        *(__half2*)(cp0 + 8 * j + 2 * tg)          = v0;
        *(__half2*)(cp0 + 8 * CC + 8 * j + 2 * tg) = v1;
    }
}

// ---------------------------------------------------------------------------
extern "C" void kernel_launch(void* const* d_in, const int* in_sizes, int n_in,
                              void* d_out, int out_size) {
    const float* hs  = (const float*)d_in[0];
    const float* Wq  = (const float*)d_in[1];
    const float* Wk  = (const float*)d_in[2];
    const float* Wv  = (const float*)d_in[3];
    const float* Wo  = (const float*)d_in[4];
    const float* bo  = (const float*)d_in[5];
    const float* Kbg = (const float*)d_in[6];
    const float* Vbg = (const float*)d_in[7];
    float* out = (float*)d_out;

    __half *gqh, *ghsh, *gwh, *gctxh, *gkh, *gvh;
    cudaGetSymbolAddress((void**)&gqh,   g_qh);
    cudaGetSymbolAddress((void**)&ghsh,  g_hsh);
    cudaGetSymbolAddress((void**)&gwh,   g_wh);
    cudaGetSymbolAddress((void**)&gctxh, g_ctxh);
    cudaGetSymbolAddress((void**)&gkh,   g_kh);
    cudaGetSymbolAddress((void**)&gvh,   g_vh);

    const __half* whQ = gwh;
    const __half* whK = gwh + (size_t)CC * CC;
    const __half* whV = gwh + 2 * (size_t)CC * CC;
    const __half* whO = gwh + 3 * (size_t)CC * CC;

    // smem sizes
    const int smem4 = 3 * (128 * APADH + BKH * BPADH) * 2;   // 56832
    const int smem2 = 3 * (64 * APADH + BKH * BPADH) * 2;    // 41472
    const int smemF = 3 * KVSTG;                             // 55296
    cudaFuncSetAttribute(hgemm_kernel<4>,
                         cudaFuncAttributeMaxDynamicSharedMemorySize, smem4);
    cudaFuncSetAttribute(flash_tc_kernel,
                         cudaFuncAttributeMaxDynamicSharedMemorySize, smemF);

    // 0. Convert hs + weights to fp16
    {
        int total = HS_N8 + 4 * W_N8;
        cvt_kernel<<<(total + 255) / 256, 256>>>(hs, Wq, Wk, Wv, Wo);
    }

    // 1. Bank KV pool -> fp16 rows [1024..1280) of g_kh/g_vh
    {
        int total = BANK * LPOOL * DH;
        pool_kernel<<<(total + 255) / 256, 256>>>(Kbg, Vbg);
    }

    // 2. Fused QKV projections (fp16 TC, 3-stage, 1 barrier/tile);
    //    Q -> fp16 prescaled, K/V -> head-major fp16
    {
        dim3 grid(3 * NTN, MROWS / 128);   // (30, 32)
        hgemm_kernel<4><<<grid, 256, smem4>>>(ghsh, whQ, whK, whV, nullptr,
                                              nullptr, gqh, gkh, gvh,
                                              MROWS, CC, CC);
    }

    // 3. Flash attention (fp16 HMMA, 128 q rows/CTA, 3-stage KV)
    {
        dim3 grid(LL / 128, BHH);   // (8, 80)
        flash_tc_kernel<<<grid, 256, smemF>>>(gqh, gkh, gvh, gctxh);
    }

    // 4. Output projection + bias (fp16 HMMA MT=2, grid 640)
    {
        dim3 grid(NTN, MROWS / 64);        // (10, 64)
        hgemm_kernel<2><<<grid, 256, smem2>>>(gctxh, whO, whO, whO, bo,
                                              out, nullptr, nullptr, nullptr,
                                              MROWS, CC, CC);
    }
}

// round 17
// speedup vs baseline: 1.0078x; 1.0078x over previous
#include <cuda_runtime.h>
#include <cuda_fp16.h>
#include <cstdint>

// Problem constants
#define BB 4
#define LL 1024
#define CC 1280
#define HH 20
#define DH 64
#define BHH (BB*HH)        // 80
#define BANK 40
#define LPOOL 256          // (32/2)*(32/2)
#define LKV (LL + LPOOL)   // 1280
#define ALPHA_C 0.48f      // 0.8 * 0.6
#define QSCALE 0.125f      // 1/sqrt(64)
#define LOG2E 1.4426950408889634f

#define MROWS (BB*LL)      // 4096

// Scratch (device globals are allowed; cudaMalloc is not)
__device__ __half g_qh[MROWS*CC];             // Q fp16, pre-scaled by QSCALE*log2e
__device__ __half g_hsh[MROWS*CC];            // hs in fp16
__device__ __half g_wh[4][CC*CC];             // Wq,Wk,Wv,Wo in fp16
__device__ __half g_ctxh[MROWS*CC];           // attention output in fp16
__device__ __half g_kh[(size_t)BHH*LKV*DH];   // fused main+bank K, fp16 head-major
__device__ __half g_vh[(size_t)BHH*LKV*DH];

__device__ __forceinline__ float fp16_round(float x) {
    return __half2float(__float2half_rn(x));
}
__device__ __forceinline__ float ex2f(float x) {
    float y;
    asm("ex2.approx.ftz.f32 %0, %1;" : "=f"(y) : "f"(x));
    return y;
}
__device__ __forceinline__ void mma_f16(float* d, const unsigned* a, unsigned b0, unsigned b1) {
    asm volatile(
        "mma.sync.aligned.m16n8k16.row.col.f32.f16.f16.f32 "
        "{%0,%1,%2,%3}, {%4,%5,%6,%7}, {%8,%9}, {%0,%1,%2,%3};\n"
        : "+f"(d[0]), "+f"(d[1]), "+f"(d[2]), "+f"(d[3])
        : "r"(a[0]), "r"(a[1]), "r"(a[2]), "r"(a[3]),
          "r"(b0), "r"(b1));
}
__device__ __forceinline__ void cp16(uint32_t saddr, const void* gptr) {
    asm volatile("cp.async.cg.shared.global [%0], [%1], 16;\n"
                 :: "r"(saddr), "l"(gptr));
}
__device__ __forceinline__ void ldsm_x4(unsigned& r0, unsigned& r1, unsigned& r2,
                                        unsigned& r3, uint32_t a) {
    asm volatile("ldmatrix.sync.aligned.m8n8.x4.shared.b16 {%0,%1,%2,%3}, [%4];\n"
                 : "=r"(r0), "=r"(r1), "=r"(r2), "=r"(r3) : "r"(a));
}
__device__ __forceinline__ void ldsm_x4_t(unsigned& r0, unsigned& r1, unsigned& r2,
                                          unsigned& r3, uint32_t a) {
    asm volatile("ldmatrix.sync.aligned.m8n8.x4.trans.shared.b16 {%0,%1,%2,%3}, [%4];\n"
                 : "=r"(r0), "=r"(r1), "=r"(r2), "=r"(r3) : "r"(a));
}

// ---------------------------------------------------------------------------
// fp32 -> fp16 conversion: hs + 4 weight matrices, 8 elems/thread
// ---------------------------------------------------------------------------
#define HS_N8 (MROWS*CC/8)    // 655360
#define W_N8  (CC*CC/8)       // 204800

__global__ void cvt_kernel(const float* __restrict__ hs,
                           const float* __restrict__ Wq, const float* __restrict__ Wk,
                           const float* __restrict__ Wv, const float* __restrict__ Wo) {
    int idx = blockIdx.x * blockDim.x + threadIdx.x;
    const float* src;
    __half* dst;
    long off;
    if (idx < HS_N8) {
        src = hs; dst = g_hsh; off = (long)idx * 8;
    } else {
        int i2 = idx - HS_N8;
        int w = i2 / W_N8;
        if (w >= 4) return;
        off = (long)(i2 % W_N8) * 8;
        src = (w == 0) ? Wq : (w == 1) ? Wk : (w == 2) ? Wv : Wo;
        dst = g_wh[w];
    }
    float4 a = *(const float4*)(src + off);
    float4 b = *(const float4*)(src + off + 4);
    __half2 h0 = __floats2half2_rn(a.x, a.y);
    __half2 h1 = __floats2half2_rn(a.z, a.w);
    __half2 h2 = __floats2half2_rn(b.x, b.y);
    __half2 h3 = __floats2half2_rn(b.z, b.w);
    uint4 pack;
    pack.x = *(unsigned*)&h0; pack.y = *(unsigned*)&h1;
    pack.z = *(unsigned*)&h2; pack.w = *(unsigned*)&h3;
    *(uint4*)(dst + off) = pack;
}

// ---------------------------------------------------------------------------
// Bank KV: fp16 round -> 2x2 avg pool -> *ALPHA, write fp16 rows [1024..1279]
// of g_kh/g_vh for BOTH bh and bh+40 (bank repeats across batch).
// ---------------------------------------------------------------------------
__global__ void pool_kernel(const float* __restrict__ Kg,
                            const float* __restrict__ Vg) {
    int idx = blockIdx.x * blockDim.x + threadIdx.x;
    const int total = BANK * LPOOL * DH;
    if (idx >= total) return;
    int d  = idx % DH;
    int p  = (idx / DH) % LPOOL;
    int bh = idx / (DH * LPOOL);
    int ph = p >> 4;
    int pw = p & 15;
    int t0 = (2 * ph) * 32 + 2 * pw;
    long base = ((long)bh * LL + t0) * DH + d;

    float ks = fp16_round(Kg[base])         + fp16_round(Kg[base + DH])
             + fp16_round(Kg[base + 32*DH]) + fp16_round(Kg[base + 33*DH]);
    float vs = fp16_round(Vg[base])         + fp16_round(Vg[base + DH])
             + fp16_round(Vg[base + 32*DH]) + fp16_round(Vg[base + 33*DH]);
    __half kq = __float2half(ALPHA_C * (ks * 0.25f));
    __half vq = __float2half(ALPHA_C * (vs * 0.25f));
#pragma unroll
    for (int rep = 0; rep < 2; rep++) {
        long dst = ((long)(bh + rep * BANK) * LKV + LL + p) * DH + d;
        g_kh[dst] = kq;
        g_vh[dst] = vq;
    }
}

// ---------------------------------------------------------------------------
// fp16 tensor-core GEMM, 4-stage cp.async pipeline (2 tiles in flight), ONE
// barrier per k-tile: wait(2) -> sync -> issue(t+3) -> mma.
// MT=4 -> 128-row tile, fused QKV: mat0 -> Q fp16 prescaled, mat1/2 -> K/V
// head-major fp16. MT=2 -> 64-row tile, Wo: fp32 out + bias (grid 640).
// ---------------------------------------------------------------------------
#define BKH 32
#define APADH 40
#define BPADH 136
#define NTN (CC/128)   // 10 n-tiles per matrix
#define NSTG 4

template<int MT>
__global__ __launch_bounds__(256)
void hgemm_kernel(const __half* __restrict__ A,
                  const __half* __restrict__ W0, const __half* __restrict__ W1,
                  const __half* __restrict__ W2, const float* __restrict__ bias,
                  float* __restrict__ C0, __half* __restrict__ HQ,
                  __half* __restrict__ HK, __half* __restrict__ HV,
                  int M, int N, int K) {
    extern __shared__ __half sm[];
    constexpr int AROWS = MT * 32;
    constexpr uint32_t ASZB = AROWS * APADH * 2u;   // bytes per A stage
    constexpr uint32_t BSZB = BKH * BPADH * 2u;     // bytes per B stage

    int tid  = threadIdx.x;
    int lane = tid & 31;
    int wid  = tid >> 5;
    int wm   = wid >> 2;          // 0..1
    int wn   = wid & 3;           // 0..3
    int g    = lane >> 2;
    int tg   = lane & 3;
    int mm   = lane >> 3;         // 0..3 (ldmatrix sub-matrix)
    int r5   = lane & 7;

    int mat = blockIdx.x / NTN;
    int ntile = blockIdx.x % NTN;
    const __half* W = (mat == 0) ? W0 : (mat == 1) ? W1 : W2;

    int m0 = blockIdx.y * AROWS;
    int n0 = ntile * 128;

    // cp.async mappings (halves)
    int arow = (MT == 4) ? (tid >> 1) : (tid >> 2);
    int acol = (MT == 4) ? ((tid & 1) * 16) : ((tid & 3) * 8);
    int brow = tid >> 3;
    int bcol = (tid & 7) * 16;

    uint32_t smem_u = (uint32_t)__cvta_generic_to_shared(sm);
    uint32_t aswb = smem_u + (uint32_t)(arow * APADH + acol) * 2u;
    uint32_t bswb = smem_u + (uint32_t)NSTG * ASZB + (uint32_t)(brow * BPADH + bcol) * 2u;

    const __half* agp = A + (long)(m0 + arow) * K + acol;
    const __half* bgp = W + (long)brow * N + n0 + bcol;

    auto issue = [&](int tile, int s) {
        const __half* ag = agp + tile * BKH;
        const __half* bg = bgp + (long)tile * BKH * N;
        uint32_t ad = aswb + (uint32_t)s * ASZB;
        uint32_t bd = bswb + (uint32_t)s * BSZB;
        cp16(ad, ag);
        if (MT == 4) cp16(ad + 16, ag + 8);
        cp16(bd, bg);
        cp16(bd + 16, bg + 8);
        asm volatile("cp.async.commit_group;\n");
    };

    float acc[MT][4][4];
#pragma unroll
    for (int i = 0; i < MT; i++)
#pragma unroll
        for (int j = 0; j < 4; j++)
#pragma unroll
            for (int r = 0; r < 4; r++) acc[i][j][r] = 0.f;

    const int NT = K / BKH;   // 40

    issue(0, 0);
    issue(1, 1);
    issue(2, 2);

    for (int t = 0; t < NT; t++) {
        int s = t % NSTG;
        // tiles issued so far: 0..min(t+2, NT-1). Tile t must be complete.
        int pend = NT - 1 - t;          // tiles after t that may stay pending
        if (pend >= 2)      asm volatile("cp.async.wait_group 2;\n");
        else if (pend == 1) asm volatile("cp.async.wait_group 1;\n");
        else                asm volatile("cp.async.wait_group 0;\n");
        __syncthreads();
        // stage (t+3)%NSTG holds tile t-1; its reads finished before this barrier
        if (t + 3 < NT) issue(t + 3, (t + 3) % NSTG);

        uint32_t aS = smem_u + (uint32_t)s * ASZB;
        uint32_t bS = smem_u + (uint32_t)NSTG * ASZB + (uint32_t)s * BSZB;

#pragma unroll
        for (int tt = 0; tt < 2; tt++) {
            unsigned af[MT][4];
#pragma unroll
            for (int mf = 0; mf < MT; mf++) {
                int row = wm * (MT * 16) + mf * 16 + (mm & 1) * 8 + r5;
                uint32_t a = aS + (uint32_t)((row * APADH + tt * 16 + (mm >> 1) * 8) * 2);
                ldsm_x4(af[mf][0], af[mf][1], af[mf][2], af[mf][3], a);
            }
#pragma unroll
            for (int j2 = 0; j2 < 2; j2++) {
                unsigned b0, b1, b2, b3;
                int krow = tt * 16 + (mm & 1) * 8 + r5;
                int col  = wn * 32 + j2 * 16 + (mm >> 1) * 8;
                uint32_t a = bS + (uint32_t)((krow * BPADH + col) * 2);
                ldsm_x4_t(b0, b1, b2, b3, a);
#pragma unroll
                for (int mf = 0; mf < MT; mf++) {
                    mma_f16(acc[mf][2 * j2],     af[mf], b0, b1);
                    mma_f16(acc[mf][2 * j2 + 1], af[mf], b2, b3);
                }
            }
        }
    }

    // Epilogue
    if (MT == 2) {
        // Wo: fp32 out + bias
#pragma unroll
        for (int mf = 0; mf < MT; mf++) {
            long r0 = m0 + wm * (MT * 16) + mf * 16 + g;
#pragma unroll
            for (int nf = 0; nf < 4; nf++) {
                int c = n0 + wn * 32 + nf * 8 + tg * 2;
                float b0 = bias ? bias[c] : 0.f;
                float b1 = bias ? bias[c + 1] : 0.f;
                float2 v0 = {acc[mf][nf][0] + b0, acc[mf][nf][1] + b1};
                float2 v1 = {acc[mf][nf][2] + b0, acc[mf][nf][3] + b1};
                *(float2*)(C0 + r0 * N + c)       = v0;
                *(float2*)(C0 + (r0 + 8) * N + c) = v1;
            }
        }
    } else if (mat == 0) {
        // Q: fp16, pre-scaled by QSCALE*log2e, [M, C] row-major
        const float sca = QSCALE * LOG2E;
#pragma unroll
        for (int mf = 0; mf < MT; mf++) {
            long r0 = m0 + wm * (MT * 16) + mf * 16 + g;
#pragma unroll
            for (int nf = 0; nf < 4; nf++) {
                int c = n0 + wn * 32 + nf * 8 + tg * 2;
#pragma unroll
                for (int rr = 0; rr < 2; rr++) {
                    long row = r0 + rr * 8;
                    __half2 hv = __floats2half2_rn(acc[mf][nf][rr * 2] * sca,
                                                   acc[mf][nf][rr * 2 + 1] * sca);
                    *(__half2*)(HQ + row * N + c) = hv;
                }
            }
        }
    } else {
        __half* H = (mat == 1) ? HK : HV;
#pragma unroll
        for (int mf = 0; mf < MT; mf++) {
            int r0 = m0 + wm * (MT * 16) + mf * 16 + g;
#pragma unroll
            for (int nf = 0; nf < 4; nf++) {
                int c = n0 + wn * 32 + nf * 8 + tg * 2;
                int h = c >> 6, d = c & 63;
#pragma unroll
                for (int rr = 0; rr < 2; rr++) {
                    int row = r0 + rr * 8;
                    int b = row >> 10, l = row & 1023;
                    long dst = ((long)(b * HH + h) * LKV + l) * DH + d;
                    __half2 hv = __floats2half2_rn(acc[mf][nf][rr * 2],
                                                   acc[mf][nf][rr * 2 + 1]);
                    *(__half2*)(&H[dst]) = hv;
                }
            }
        }
    }
}

// ---------------------------------------------------------------------------
// Flash attention, fp16 HMMA. Block = (head, 128 q rows), 8 warps, 4-stage KV
// pipeline (2 tiles in flight), one barrier per KV tile. Q pre-scaled fp16.
// ---------------------------------------------------------------------------
#define KPAD 72
#define KVSTG (2 * 64 * KPAD * 2)   // bytes per stage (K+V) = 18432

__global__ __launch_bounds__(256)
void flash_tc_kernel(const __half* __restrict__ qh, const __half* __restrict__ kh,
                     const __half* __restrict__ vh, __half* __restrict__ ctxh) {
    extern __shared__ __half skv[];

    int tid  = threadIdx.x;
    int lane = tid & 31;
    int w    = tid >> 5;
    int g    = lane >> 2;
    int tg   = lane & 3;
    int mm   = lane >> 3;
    int r5   = lane & 7;
    int bh = blockIdx.y;
    int bb = bh / HH;
    int hh = bh % HH;
    int q0 = blockIdx.x * 128;
    int qrow = q0 + w * 16 + g;

    // Q fragments: direct fp16 loads (pre-scaled in GEMM epilogue)
    unsigned qa[4][4];
    {
        const __half* qp = qh + ((long)bb * LL + qrow) * CC + hh * DH;
#pragma unroll
        for (int t = 0; t < 4; t++) {
            qa[t][0] = *(const unsigned*)(qp + 16 * t + 2 * tg);
            qa[t][1] = *(const unsigned*)(qp + 8 * CC + 16 * t + 2 * tg);
            qa[t][2] = *(const unsigned*)(qp + 16 * t + 8 + 2 * tg);
            qa[t][3] = *(const unsigned*)(qp + 8 * CC + 16 * t + 8 + 2 * tg);
        }
    }

    int tsel = tid >> 7;
    int idxl = tid & 127;
    int lrow = idxl >> 1;
    int lhf  = idxl & 1;
    const __half* gsrc0 = (tsel ? vh : kh) + ((long)bh * LKV + lrow) * DH + lhf * 32;
    uint32_t sbase = (uint32_t)__cvta_generic_to_shared(skv);
    uint32_t sdst0 = sbase + (uint32_t)(tsel * (64 * KPAD) + lrow * KPAD + lhf * 32) * 2u;

    auto issue = [&](int tile, int s) {
        const __half* src = gsrc0 + (long)tile * 64 * DH;
        uint32_t dd = sdst0 + (uint32_t)s * KVSTG;
#pragma unroll
        for (int i = 0; i < 4; i++) cp16(dd + i * 16, src + i * 8);
        asm volatile("cp.async.commit_group;\n");
    };

    float m0v = -1e30f, m1v = -1e30f, l0 = 0.f, l1 = 0.f;
    float O[8][4];
#pragma unroll
    for (int j = 0; j < 8; j++)
#pragma unroll
        for (int r = 0; r < 4; r++) O[j][r] = 0.f;

    const int NT = LKV / 64;   // 20

    issue(0, 0);
    issue(1, 1);
    issue(2, 2);

    for (int t = 0; t < NT; t++) {
        int s = t % NSTG;
        int pend = NT - 1 - t;
        if (pend >= 2)      asm volatile("cp.async.wait_group 2;\n");
        else if (pend == 1) asm volatile("cp.async.wait_group 1;\n");
        else                asm volatile("cp.async.wait_group 0;\n");
        __syncthreads();
        if (t + 3 < NT) issue(t + 3, (t + 3) % NSTG);

        uint32_t kbase = sbase + (uint32_t)s * KVSTG;
        uint32_t vbase = kbase + (uint32_t)(64 * KPAD) * 2u;

        // S = Q K^T (log2 domain)
        float sacc[8][4];
#pragma unroll
        for (int j = 0; j < 8; j++)
#pragma unroll
            for (int r = 0; r < 4; r++) sacc[j][r] = 0.f;

#pragma unroll
        for (int tt = 0; tt < 4; tt++) {
#pragma unroll
            for (int j2 = 0; j2 < 4; j2++) {
                unsigned b0, b1, b2, b3;
                uint32_t a = kbase +
                    (uint32_t)(((j2 * 16 + (mm >> 1) * 8 + r5) * KPAD
                                + tt * 16 + (mm & 1) * 8) * 2);
                ldsm_x4(b0, b1, b2, b3, a);
                mma_f16(sacc[2 * j2],     qa[tt], b0, b1);
                mma_f16(sacc[2 * j2 + 1], qa[tt], b2, b3);
            }
        }

        // Online softmax
        float mx0 = -1e30f, mx1 = -1e30f;
#pragma unroll
        for (int j = 0; j < 8; j++) {
            mx0 = fmaxf(mx0, fmaxf(sacc[j][0], sacc[j][1]));
            mx1 = fmaxf(mx1, fmaxf(sacc[j][2], sacc[j][3]));
        }
        mx0 = fmaxf(mx0, __shfl_xor_sync(0xffffffffu, mx0, 1));
        mx0 = fmaxf(mx0, __shfl_xor_sync(0xffffffffu, mx0, 2));
        mx1 = fmaxf(mx1, __shfl_xor_sync(0xffffffffu, mx1, 1));
        mx1 = fmaxf(mx1, __shfl_xor_sync(0xffffffffu, mx1, 2));

        float mn0 = fmaxf(m0v, mx0);
        float mn1 = fmaxf(m1v, mx1);
        float sc0 = ex2f(m0v - mn0);
        float sc1 = ex2f(m1v - mn1);
        m0v = mn0; m1v = mn1;

        // exp in place
        float su0 = 0.f, su1 = 0.f;
#pragma unroll
        for (int j = 0; j < 8; j++) {
            sacc[j][0] = ex2f(sacc[j][0] - mn0);
            sacc[j][1] = ex2f(sacc[j][1] - mn0);
            sacc[j][2] = ex2f(sacc[j][2] - mn1);
            sacc[j][3] = ex2f(sacc[j][3] - mn1);
            su0 += sacc[j][0] + sacc[j][1];
            su1 += sacc[j][2] + sacc[j][3];
        }
        su0 += __shfl_xor_sync(0xffffffffu, su0, 1);
        su0 += __shfl_xor_sync(0xffffffffu, su0, 2);
        su1 += __shfl_xor_sync(0xffffffffu, su1, 1);
        su1 += __shfl_xor_sync(0xffffffffu, su1, 2);
        l0 = l0 * sc0 + su0;
        l1 = l1 * sc1 + su1;

#pragma unroll
        for (int j = 0; j < 8; j++) {
            O[j][0] *= sc0; O[j][1] *= sc0;
            O[j][2] *= sc1; O[j][3] *= sc1;
        }

        // Pack P fragments directly from accumulators (C layout == A layout)
        unsigned paf[4][4];
#pragma unroll
        for (int tt = 0; tt < 4; tt++) {
            __half2 a0 = __floats2half2_rn(sacc[2*tt][0],   sacc[2*tt][1]);
            __half2 a1 = __floats2half2_rn(sacc[2*tt][2],   sacc[2*tt][3]);
            __half2 a2 = __floats2half2_rn(sacc[2*tt+1][0], sacc[2*tt+1][1]);
            __half2 a3 = __floats2half2_rn(sacc[2*tt+1][2], sacc[2*tt+1][3]);
            paf[tt][0] = *(unsigned*)&a0;
            paf[tt][1] = *(unsigned*)&a1;
            paf[tt][2] = *(unsigned*)&a2;
            paf[tt][3] = *(unsigned*)&a3;
        }

        // O += P V  (V^T fragments via ldmatrix.trans)
#pragma unroll
        for (int tt = 0; tt < 4; tt++) {
#pragma unroll
            for (int j2 = 0; j2 < 4; j2++) {
                unsigned b0, b1, b2, b3;
                uint32_t a = vbase +
                    (uint32_t)(((tt * 16 + (mm & 1) * 8 + r5) * KPAD
                                + j2 * 16 + (mm >> 1) * 8) * 2);
                ldsm_x4_t(b0, b1, b2, b3, a);
                mma_f16(O[2 * j2],     paf[tt], b0, b1);
                mma_f16(O[2 * j2 + 1], paf[tt], b2, b3);
            }
        }
    }

    // Normalize + write ctx (fp16) in [B, L, H*Dh]
    float inv0 = 1.f / l0;
    float inv1 = 1.f / l1;
    __half* cp0 = ctxh + ((long)bb * LL + qrow) * CC + hh * DH;
#pragma unroll
    for (int j = 0; j < 8; j++) {
        __half2 v0 = __floats2half2_rn(O[j][0] * inv0, O[j][1] * inv0);
        __half2 v1 = __floats2half2_rn(O[j][2] * inv1, O[j][3] * inv1);
        *(__half2*)(cp0 + 8 * j + 2 * tg)          = v0;
        *(__half2*)(cp0 + 8 * CC + 8 * j + 2 * tg) = v1;
    }
}

// ---------------------------------------------------------------------------
extern "C" void kernel_launch(void* const* d_in, const int* in_sizes, int n_in,
                              void* d_out, int out_size) {
    const float* hs  = (const float*)d_in[0];
    const float* Wq  = (const float*)d_in[1];
    const float* Wk  = (const float*)d_in[2];
    const float* Wv  = (const float*)d_in[3];
    const float* Wo  = (const float*)d_in[4];
    const float* bo  = (const float*)d_in[5];
    const float* Kbg = (const float*)d_in[6];
    const float* Vbg = (const float*)d_in[7];
    float* out = (float*)d_out;

    __half *gqh, *ghsh, *gwh, *gctxh, *gkh, *gvh;
    cudaGetSymbolAddress((void**)&gqh,   g_qh);
    cudaGetSymbolAddress((void**)&ghsh,  g_hsh);
    cudaGetSymbolAddress((void**)&gwh,   g_wh);
    cudaGetSymbolAddress((void**)&gctxh, g_ctxh);
    cudaGetSymbolAddress((void**)&gkh,   g_kh);
    cudaGetSymbolAddress((void**)&gvh,   g_vh);

    const __half* whQ = gwh;
    const __half* whK = gwh + (size_t)CC * CC;
    const __half* whV = gwh + 2 * (size_t)CC * CC;
    const __half* whO = gwh + 3 * (size_t)CC * CC;

    // smem sizes (4 stages)
    const int smem4 = NSTG * (128 * APADH + BKH * BPADH) * 2;   // 75776
    const int smem2 = NSTG * (64 * APADH + BKH * BPADH) * 2;    // 55296
    const int smemF = NSTG * KVSTG;                             // 73728
    cudaFuncSetAttribute(hgemm_kernel<4>,
                         cudaFuncAttributeMaxDynamicSharedMemorySize, smem4);
    cudaFuncSetAttribute(hgemm_kernel<2>,
                         cudaFuncAttributeMaxDynamicSharedMemorySize, smem2);
    cudaFuncSetAttribute(flash_tc_kernel,
                         cudaFuncAttributeMaxDynamicSharedMemorySize, smemF);

    // 0. Convert hs + weights to fp16
    {
        int total = HS_N8 + 4 * W_N8;
        cvt_kernel<<<(total + 255) / 256, 256>>>(hs, Wq, Wk, Wv, Wo);
    }

    // 1. Bank KV pool -> fp16 rows [1024..1280) of g_kh/g_vh
    {
        int total = BANK * LPOOL * DH;
        pool_kernel<<<(total + 255) / 256, 256>>>(Kbg, Vbg);
    }

    // 2. Fused QKV projections (fp16 TC, 4-stage, 1 barrier/tile);
    //    Q -> fp16 prescaled, K/V -> head-major fp16
    {
        dim3 grid(3 * NTN, MROWS / 128);   // (30, 32)
        hgemm_kernel<4><<<grid, 256, smem4>>>(ghsh, whQ, whK, whV, nullptr,
                                              nullptr, gqh, gkh, gvh,
                                              MROWS, CC, CC);
    }

    // 3. Flash attention (fp16 HMMA, 128 q rows/CTA, 4-stage KV)
    {
        dim3 grid(LL / 128, BHH);   // (8, 80)
        flash_tc_kernel<<<grid, 256, smemF>>>(gqh, gkh, gvh, gctxh);
    }

    // 4. Output projection + bias (fp16 HMMA MT=2, 4-stage, grid 640)
    {
        dim3 grid(NTN, MROWS / 64);        // (10, 64)
        hgemm_kernel<2><<<grid, 256, smem2>>>(gctxh, whO, whO, whO, bo,
                                              out, nullptr, nullptr, nullptr,
                                              MROWS, CC, CC);
    }
}